// round 15
// baseline (speedup 1.0000x reference)
#include <cuda_runtime.h>
#include <cuda_bf16.h>
#include <cstdint>
#include <cstddef>

#define NMAX 50000
#define EMAX 600000
#define D 128

// ---------------------------------------------------------------------------
// Device scratch.  "p" buffers are packed bf16x2 planes: [row][k2] uint32.
// ---------------------------------------------------------------------------
__device__ __align__(16) float g_dinv[NMAX];
__device__ __align__(16) float g_g1[NMAX * D];   // h1 = x@W1 fp32
__device__ __align__(16) float g_g2[NMAX * D];   // h2 = x1@W2 fp32
__device__ __align__(16) uint32_t g_x1ph[NMAX * 64], g_x1pl[NMAX * 64];
__device__ __align__(16) uint32_t g_y2ph[NMAX * 64], g_y2pl[NMAX * 64];
// weights transposed to [n][k2] planes
__device__ __align__(16) uint32_t g_w1ph[128 * 64],  g_w1pl[128 * 64];
__device__ __align__(16) uint32_t g_w2ph[128 * 64],  g_w2pl[128 * 64];
__device__ __align__(16) uint32_t g_wlph[128 * 128], g_wlpl[128 * 128];
// CSR (by destination).  g_cnt is zero at load and re-zeroed by gemm3 every
// pass, so hist may legally run first in each invocation.
__device__ int g_cnt[NMAX];
__device__ int g_wr[NMAX];
__device__ int g_rowptr[NMAX + 1];
__device__ int g_srcidx[EMAX];

// bf16 split: pack 2 floats -> hi bf16x2 + lo bf16x2 (low 16 bits = first val)
__device__ __forceinline__ void split2(float a, float b, uint32_t& hi, uint32_t& lo) {
    __nv_bfloat16 ha = __float2bfloat16_rn(a), hb = __float2bfloat16_rn(b);
    float ra = a - __bfloat162float(ha), rb = b - __bfloat162float(hb);
    __nv_bfloat16 la = __float2bfloat16_rn(ra), lb = __float2bfloat16_rn(rb);
    hi = (uint32_t)__bfloat16_as_ushort(ha) | ((uint32_t)__bfloat16_as_ushort(hb) << 16);
    lo = (uint32_t)__bfloat16_as_ushort(la) | ((uint32_t)__bfloat16_as_ushort(lb) << 16);
}

// ---------------------------------------------------------------------------
// Prep: weights -> transposed packed hi/lo planes (32768 threads)
// ---------------------------------------------------------------------------
__global__ void prep_w_kernel(const float* __restrict__ W1,
                              const float* __restrict__ W2,
                              const float* __restrict__ Wl) {
    int idx = blockIdx.x * blockDim.x + threadIdx.x;
    if (idx < 8192) {                       // W1 [128][128] -> [n][64]
        int nn = idx & 127, k2 = idx >> 7;
        uint32_t h, l;
        split2(W1[(2 * k2) * 128 + nn], W1[(2 * k2 + 1) * 128 + nn], h, l);
        g_w1ph[nn * 64 + k2] = h; g_w1pl[nn * 64 + k2] = l;
    } else if (idx < 16384) {               // W2
        int r = idx - 8192;
        int nn = r & 127, k2 = r >> 7;
        uint32_t h, l;
        split2(W2[(2 * k2) * 128 + nn], W2[(2 * k2 + 1) * 128 + nn], h, l);
        g_w2ph[nn * 64 + k2] = h; g_w2pl[nn * 64 + k2] = l;
    } else if (idx < 32768) {               // Wl [256][128] -> [n][128]
        int r = idx - 16384;
        int nn = r & 127, k2 = r >> 7;      // k2 in 0..127
        uint32_t h, l;
        split2(Wl[(2 * k2) * 128 + nn], Wl[(2 * k2 + 1) * 128 + nn], h, l);
        g_wlph[nn * 128 + k2] = h; g_wlpl[nn * 128 + k2] = l;
    }
}

// ---------------------------------------------------------------------------
// CSR build (edge_index is INT32), 4 edges/thread
// ---------------------------------------------------------------------------
__global__ void hist_kernel(const int* __restrict__ ei, int E, int n) {
    int e = (blockIdx.x * blockDim.x + threadIdx.x) * 4;
    if (e + 4 <= E) {
        int4 c = *(const int4*)(ei + E + e);
        if ((unsigned)c.x < (unsigned)n) atomicAdd(&g_cnt[c.x], 1);
        if ((unsigned)c.y < (unsigned)n) atomicAdd(&g_cnt[c.y], 1);
        if ((unsigned)c.z < (unsigned)n) atomicAdd(&g_cnt[c.z], 1);
        if ((unsigned)c.w < (unsigned)n) atomicAdd(&g_cnt[c.w], 1);
    } else {
        for (; e < E; e++) {
            int c = ei[E + e];
            if ((unsigned)c < (unsigned)n) atomicAdd(&g_cnt[c], 1);
        }
    }
}

__global__ __launch_bounds__(1024) void scan_kernel(int n) {
    __shared__ int s[1024];
    const int t = threadIdx.x;
    const int C = (n + 1023) / 1024;
    const int start = t * C, end = min(start + C, n);
    int sum = 0;
    for (int i = start; i < end; i++) sum += g_cnt[i];
    s[t] = sum;
    __syncthreads();
    for (int off = 1; off < 1024; off <<= 1) {
        int v = s[t];
        int o = (t >= off) ? s[t - off] : 0;
        __syncthreads();
        s[t] = v + o;
        __syncthreads();
    }
    int run = s[t] - sum;
    for (int i = start; i < end; i++) {
        g_rowptr[i] = run;
        g_wr[i] = run;
        g_dinv[i] = rsqrtf((float)(g_cnt[i] + 1));
        run += g_cnt[i];
    }
    if (t == 0) g_rowptr[n] = s[1023];
}

__global__ void place_kernel(const int* __restrict__ ei, int E, int n) {
    int e = (blockIdx.x * blockDim.x + threadIdx.x) * 4;
    if (e + 4 <= E) {
        int4 c = *(const int4*)(ei + E + e);
        int4 r = *(const int4*)(ei + e);
        if ((unsigned)c.x < (unsigned)n && (unsigned)r.x < (unsigned)n)
            g_srcidx[atomicAdd(&g_wr[c.x], 1)] = r.x;
        if ((unsigned)c.y < (unsigned)n && (unsigned)r.y < (unsigned)n)
            g_srcidx[atomicAdd(&g_wr[c.y], 1)] = r.y;
        if ((unsigned)c.z < (unsigned)n && (unsigned)r.z < (unsigned)n)
            g_srcidx[atomicAdd(&g_wr[c.z], 1)] = r.z;
        if ((unsigned)c.w < (unsigned)n && (unsigned)r.w < (unsigned)n)
            g_srcidx[atomicAdd(&g_wr[c.w], 1)] = r.w;
    } else {
        for (; e < E; e++) {
            int c = ei[E + e], r = ei[e];
            if ((unsigned)c < (unsigned)n && (unsigned)r < (unsigned)n)
                g_srcidx[atomicAdd(&g_wr[c], 1)] = r;
        }
    }
}

// ---------------------------------------------------------------------------
// Gather: TWO warps per node, each handling 64 features (float2 per lane).
// Fused relu/bias/dinv; emits packed bf16x2 hi/lo planes.
// 8/4/2/1 unroll ladder so the Poisson degree tail stays batched.
// layer 0: h=g_g1, bias=b1 -> x1 planes.  layer 1: h=g_g2, bias=b2 -> y2.
// ---------------------------------------------------------------------------
__global__ __launch_bounds__(256) void gather_kernel(int layer, int n,
                                                     const float* __restrict__ bias) {
    int gw = (blockIdx.x * blockDim.x + threadIdx.x) >> 5;
    int node = gw >> 1, half = gw & 1;
    int lane = threadIdx.x & 31;
    if (node >= n) return;

    const float* __restrict__ h = (layer == 0) ? g_g1 : g_g2;
    uint32_t* __restrict__ oh = (layer == 0) ? g_x1ph : g_y2ph;
    uint32_t* __restrict__ ol = (layer == 0) ? g_x1pl : g_y2pl;

    const int f = half * 64 + lane * 2;      // this lane's 2 features
    size_t base = (size_t)node * D + f;
    float dn = g_dinv[node];
    float2 sv = *(const float2*)(h + base);
    float2 acc = make_float2(sv.x * dn, sv.y * dn);

    int s = g_rowptr[node], e = g_rowptr[node + 1];
    int i = s;
    for (; i + 8 <= e; i += 8) {
        int si[8]; float di[8]; float2 vi[8];
#pragma unroll
        for (int j = 0; j < 8; j++) si[j] = g_srcidx[i + j];
#pragma unroll
        for (int j = 0; j < 8; j++) di[j] = g_dinv[si[j]];
#pragma unroll
        for (int j = 0; j < 8; j++)
            vi[j] = *(const float2*)(h + (size_t)si[j] * D + f);
#pragma unroll
        for (int j = 0; j < 8; j++) {
            acc.x += vi[j].x * di[j];
            acc.y += vi[j].y * di[j];
        }
    }
    for (; i + 4 <= e; i += 4) {
        int si[4]; float di[4]; float2 vi[4];
#pragma unroll
        for (int j = 0; j < 4; j++) si[j] = g_srcidx[i + j];
#pragma unroll
        for (int j = 0; j < 4; j++) di[j] = g_dinv[si[j]];
#pragma unroll
        for (int j = 0; j < 4; j++)
            vi[j] = *(const float2*)(h + (size_t)si[j] * D + f);
#pragma unroll
        for (int j = 0; j < 4; j++) {
            acc.x += vi[j].x * di[j];
            acc.y += vi[j].y * di[j];
        }
    }
    if (i + 2 <= e) {
        int s0 = g_srcidx[i], s1 = g_srcidx[i + 1];
        float d0 = g_dinv[s0], d1 = g_dinv[s1];
        float2 v0 = *(const float2*)(h + (size_t)s0 * D + f);
        float2 v1 = *(const float2*)(h + (size_t)s1 * D + f);
        acc.x += v0.x * d0 + v1.x * d1;
        acc.y += v0.y * d0 + v1.y * d1;
        i += 2;
    }
    if (i < e) {
        int s0 = g_srcidx[i];
        float d0 = g_dinv[s0];
        float2 v0 = *(const float2*)(h + (size_t)s0 * D + f);
        acc.x += v0.x * d0;
        acc.y += v0.y * d0;
    }

    float2 bb = *(const float2*)(bias + f);
    float r0 = fmaxf(fmaf(dn, acc.x, bb.x), 0.f);
    float r1 = fmaxf(fmaf(dn, acc.y, bb.y), 0.f);
    uint32_t hh, ll;
    split2(r0, r1, hh, ll);
    size_t pidx = (size_t)node * 64 + half * 32 + lane;
    oh[pidx] = hh;
    ol[pidx] = ll;
}

// ---------------------------------------------------------------------------
// bf16 m16n8k16 tensor GEMM, 3-term hi/lo split.
// Block 256 thr (8 warps), tile 128(M)x128(N); warp w: m0w=(w&3)*32, n0w=(w>>2)*64.
// MODE 0: A = fp32 x (split inline), B=W1 planes -> g_g1.
// MODE 1: A = x1 planes,             B=W2 planes -> g_g2.
// MODE 2: K2=128, A = x1|y2 planes,  B=Wl planes -> out+bl.  Zeroes g_cnt.
// ---------------------------------------------------------------------------
__device__ __forceinline__ void mma16(float* c, const uint32_t* a,
                                      uint32_t b0, uint32_t b1) {
    asm("mma.sync.aligned.m16n8k16.row.col.f32.bf16.bf16.f32 "
        "{%0,%1,%2,%3}, {%4,%5,%6,%7}, {%8,%9}, {%0,%1,%2,%3};"
        : "+f"(c[0]), "+f"(c[1]), "+f"(c[2]), "+f"(c[3])
        : "r"(a[0]), "r"(a[1]), "r"(a[2]), "r"(a[3]), "r"(b0), "r"(b1));
}

__device__ __forceinline__ void stage_plane(uint32_t (*dst)[132],
                                            const uint32_t* __restrict__ src,
                                            int m0, int nvalid, int strideK2,
                                            int k2off) {
    const int t = threadIdx.x;
#pragma unroll
    for (int i = 0; i < 2; i++) {
        int idx = t + i * 256;          // 512 uint4 = 128 rows x 16 k2
        int m = idx >> 2, q = idx & 3;
        uint4 v = make_uint4(0, 0, 0, 0);
        int gm = m0 + m;
        if (gm < nvalid)
            v = *(const uint4*)(src + (size_t)gm * strideK2 + k2off + q * 4);
        dst[q * 4 + 0][m] = v.x; dst[q * 4 + 1][m] = v.y;
        dst[q * 4 + 2][m] = v.z; dst[q * 4 + 3][m] = v.w;
    }
}

// stage A from fp32 source with inline bf16 hi/lo split (MODE 0)
__device__ __forceinline__ void stage_split(uint32_t (*dh)[132], uint32_t (*dl)[132],
                                            const float* __restrict__ src,
                                            int m0, int nvalid, int kc2) {
    const int t = threadIdx.x;
#pragma unroll
    for (int i = 0; i < 4; i++) {
        int idx = t + i * 256;          // 1024 float4 = 128 rows x 8 float4
        int m = idx >> 3, q = idx & 7;
        float4 v = make_float4(0.f, 0.f, 0.f, 0.f);
        int gm = m0 + m;
        if (gm < nvalid)
            v = *(const float4*)(src + (size_t)gm * D + kc2 * 2 + q * 4);
        uint32_t h0, l0, h1, l1;
        split2(v.x, v.y, h0, l0);
        split2(v.z, v.w, h1, l1);
        dh[2 * q + 0][m] = h0; dl[2 * q + 0][m] = l0;
        dh[2 * q + 1][m] = h1; dl[2 * q + 1][m] = l1;
    }
}

template <int MODE>
__global__ __launch_bounds__(256) void gemm_bf16(
    const float* __restrict__ Ax,        // MODE0: fp32 x
    const float* __restrict__ bias_out,  // MODE2: bl
    float* __restrict__ outp,            // MODE2: out
    int n)
{
    constexpr int K2 = (MODE == 2) ? 128 : 64;
    __shared__ uint32_t sAh[16][132], sAl[16][132];
    __shared__ uint32_t sBh[16][132], sBl[16][132];

    const int t = threadIdx.x;
    const int lane = t & 31, w = t >> 5;
    const int g = lane >> 2, q4 = lane & 3;
    const int m0w = (w & 3) * 32, n0w = (w >> 2) * 64;
    const int m0 = blockIdx.x * 128;

    // MODE 2: re-zero g_cnt for the next pass
    if (MODE == 2) {
        for (int i = blockIdx.x * blockDim.x + t; i < n; i += gridDim.x * blockDim.x)
            g_cnt[i] = 0;
    }

    float acc[2][8][4];
#pragma unroll
    for (int i = 0; i < 2; i++)
#pragma unroll
        for (int j = 0; j < 8; j++)
#pragma unroll
            for (int k = 0; k < 4; k++) acc[i][j][k] = 0.0f;

    for (int kc2 = 0; kc2 < K2; kc2 += 16) {
        if (MODE == 0) {
            stage_split(sAh, sAl, Ax, m0, n, kc2);
            stage_plane(sBh, g_w1ph, 0, 128, 64, kc2);
            stage_plane(sBl, g_w1pl, 0, 128, 64, kc2);
        } else if (MODE == 1) {
            stage_plane(sAh, g_x1ph, m0, n, 64, kc2);
            stage_plane(sAl, g_x1pl, m0, n, 64, kc2);
            stage_plane(sBh, g_w2ph, 0, 128, 64, kc2);
            stage_plane(sBl, g_w2pl, 0, 128, 64, kc2);
        } else {
            const uint32_t* ah = (kc2 < 64) ? g_x1ph : g_y2ph;
            const uint32_t* al = (kc2 < 64) ? g_x1pl : g_y2pl;
            int off = (kc2 < 64) ? kc2 : kc2 - 64;
            stage_plane(sAh, ah, m0, n, 64, off);
            stage_plane(sAl, al, m0, n, 64, off);
            stage_plane(sBh, g_wlph, 0, 128, 128, kc2);
            stage_plane(sBl, g_wlpl, 0, 128, 128, kc2);
        }
        __syncthreads();

#pragma unroll
        for (int kb2 = 0; kb2 < 16; kb2 += 8) {
            uint32_t ah[2][4], al[2][4];
#pragma unroll
            for (int ma = 0; ma < 2; ma++) {
                int mm = m0w + ma * 16 + g;
                ah[ma][0] = sAh[kb2 + q4][mm];
                ah[ma][1] = sAh[kb2 + q4][mm + 8];
                ah[ma][2] = sAh[kb2 + q4 + 4][mm];
                ah[ma][3] = sAh[kb2 + q4 + 4][mm + 8];
                al[ma][0] = sAl[kb2 + q4][mm];
                al[ma][1] = sAl[kb2 + q4][mm + 8];
                al[ma][2] = sAl[kb2 + q4 + 4][mm];
                al[ma][3] = sAl[kb2 + q4 + 4][mm + 8];
            }
#pragma unroll
            for (int na = 0; na < 8; na++) {
                int nn = n0w + na * 8 + g;
                uint32_t bh0 = sBh[kb2 + q4][nn];
                uint32_t bh1 = sBh[kb2 + q4 + 4][nn];
                uint32_t bl0 = sBl[kb2 + q4][nn];
                uint32_t bl1 = sBl[kb2 + q4 + 4][nn];
#pragma unroll
                for (int ma = 0; ma < 2; ma++) {
                    mma16(acc[ma][na], ah[ma], bh0, bh1);  // hi*hi
                    mma16(acc[ma][na], al[ma], bh0, bh1);  // lo*hi
                    mma16(acc[ma][na], ah[ma], bl0, bl1);  // hi*lo
                }
            }
        }
        __syncthreads();
    }

    // ---- epilogue ----
    float* dst = (MODE == 0) ? g_g1 : (MODE == 1) ? g_g2 : outp;
#pragma unroll
    for (int ma = 0; ma < 2; ma++) {
        int mlo = m0 + m0w + ma * 16 + g;
        int mhi = mlo + 8;
#pragma unroll
        for (int na = 0; na < 8; na++) {
            int nc = n0w + na * 8 + 2 * q4;
            float b0 = 0.f, b1 = 0.f;
            if (MODE == 2) { b0 = bias_out[nc]; b1 = bias_out[nc + 1]; }
            if (mlo < n) {
                float2 v = make_float2(acc[ma][na][0] + b0, acc[ma][na][1] + b1);
                *(float2*)(dst + (size_t)mlo * D + nc) = v;
            }
            if (mhi < n) {
                float2 v = make_float2(acc[ma][na][2] + b0, acc[ma][na][3] + b1);
                *(float2*)(dst + (size_t)mhi * D + nc) = v;
            }
        }
    }
}

// ---------------------------------------------------------------------------
// Launch: single stream, no host state, graph-capture safe.  9 launches.
// ---------------------------------------------------------------------------
extern "C" void kernel_launch(void* const* d_in, const int* in_sizes, int n_in,
                              void* d_out, int out_size)
{
    const float* x  = (const float*)d_in[0];
    const int*   ei = (const int*)d_in[1];      // int32
    const float* W1 = (const float*)d_in[2];
    const float* b1 = (const float*)d_in[3];
    const float* W2 = (const float*)d_in[4];
    const float* b2 = (const float*)d_in[5];
    const float* Wl = (const float*)d_in[6];
    const float* bl = (const float*)d_in[7];
    float* out = (float*)d_out;

    const int n = in_sizes[0] / D;   // 50000
    const int E = in_sizes[1] / 2;   // 600000

    const int e4blocks = ((E + 3) / 4 + 255) / 256;
    const int gblocks = (n + 127) / 128;
    const int wblocks = (2 * n + 7) / 8;   // two warps per node

    prep_w_kernel<<<128, 256>>>(W1, W2, Wl);
    hist_kernel<<<e4blocks, 256>>>(ei, E, n);
    scan_kernel<<<1, 1024>>>(n);
    place_kernel<<<e4blocks, 256>>>(ei, E, n);

    gemm_bf16<0><<<gblocks, 256>>>(x, nullptr, nullptr, n);
    gather_kernel<<<wblocks, 256>>>(0, n, b1);
    gemm_bf16<1><<<gblocks, 256>>>(nullptr, nullptr, nullptr, n);
    gather_kernel<<<wblocks, 256>>>(1, n, b2);
    gemm_bf16<2><<<gblocks, 256>>>(nullptr, bl, out, n);
}

// round 16
// speedup vs baseline: 1.1022x; 1.1022x over previous
#include <cuda_runtime.h>
#include <cuda_bf16.h>
#include <cstdint>
#include <cstddef>

#define NMAX 50000
#define EMAX 600000
#define D 128
#define SROW 12   // smem row stride in u32: 8 k2 + 4 pad (conflict-free)

// ---------------------------------------------------------------------------
// Device scratch.  "p" buffers are packed bf16x2 planes: [row][k2] uint32.
// ---------------------------------------------------------------------------
__device__ __align__(16) float g_dinv[NMAX];
__device__ __align__(16) float g_g1[NMAX * D];   // h1 = x@W1 fp32
__device__ __align__(16) float g_g2[NMAX * D];   // h2 = x1@W2 fp32
__device__ __align__(16) uint32_t g_x1ph[NMAX * 64], g_x1pl[NMAX * 64];
__device__ __align__(16) uint32_t g_y2ph[NMAX * 64], g_y2pl[NMAX * 64];
// weights transposed to [n][k2] planes
__device__ __align__(16) uint32_t g_w1ph[128 * 64],  g_w1pl[128 * 64];
__device__ __align__(16) uint32_t g_w2ph[128 * 64],  g_w2pl[128 * 64];
__device__ __align__(16) uint32_t g_wlph[128 * 128], g_wlpl[128 * 128];
// CSR (by destination).  g_cnt zeroed by prep each pass.
__device__ int g_cnt[NMAX];
__device__ int g_wr[NMAX];
__device__ int g_rowptr[NMAX + 1];
__device__ int g_srcidx[EMAX];

// bf16 split: pack 2 floats -> hi bf16x2 + lo bf16x2 (low 16 bits = first val)
__device__ __forceinline__ void split2(float a, float b, uint32_t& hi, uint32_t& lo) {
    __nv_bfloat16 ha = __float2bfloat16_rn(a), hb = __float2bfloat16_rn(b);
    float ra = a - __bfloat162float(ha), rb = b - __bfloat162float(hb);
    __nv_bfloat16 la = __float2bfloat16_rn(ra), lb = __float2bfloat16_rn(rb);
    hi = (uint32_t)__bfloat16_as_ushort(ha) | ((uint32_t)__bfloat16_as_ushort(hb) << 16);
    lo = (uint32_t)__bfloat16_as_ushort(la) | ((uint32_t)__bfloat16_as_ushort(lb) << 16);
}

__device__ __forceinline__ void cpa16(uint32_t dst, const void* src, int szbytes) {
    asm volatile("cp.async.cg.shared.global [%0], [%1], 16, %2;"
                 :: "r"(dst), "l"(src), "r"(szbytes) : "memory");
}

// ---------------------------------------------------------------------------
// Prep: weights -> transposed packed hi/lo planes; zeroes g_cnt.
// grid covers max(n, 32768) threads.
// ---------------------------------------------------------------------------
__global__ void prep_kernel(const float* __restrict__ W1,
                            const float* __restrict__ W2,
                            const float* __restrict__ Wl, int n) {
    int idx = blockIdx.x * blockDim.x + threadIdx.x;
    if (idx < n) g_cnt[idx] = 0;
    if (idx < 8192) {                       // W1 [128][128] -> [n][64]
        int nn = idx & 127, k2 = idx >> 7;
        uint32_t h, l;
        split2(W1[(2 * k2) * 128 + nn], W1[(2 * k2 + 1) * 128 + nn], h, l);
        g_w1ph[nn * 64 + k2] = h; g_w1pl[nn * 64 + k2] = l;
    } else if (idx < 16384) {               // W2
        int r = idx - 8192;
        int nn = r & 127, k2 = r >> 7;
        uint32_t h, l;
        split2(W2[(2 * k2) * 128 + nn], W2[(2 * k2 + 1) * 128 + nn], h, l);
        g_w2ph[nn * 64 + k2] = h; g_w2pl[nn * 64 + k2] = l;
    } else if (idx < 32768) {               // Wl [256][128] -> [n][128]
        int r = idx - 16384;
        int nn = r & 127, k2 = r >> 7;      // k2 in 0..127
        uint32_t h, l;
        split2(Wl[(2 * k2) * 128 + nn], Wl[(2 * k2 + 1) * 128 + nn], h, l);
        g_wlph[nn * 128 + k2] = h; g_wlpl[nn * 128 + k2] = l;
    }
}

// ---------------------------------------------------------------------------
// CSR build (edge_index is INT32), 4 edges/thread
// ---------------------------------------------------------------------------
__global__ void hist_kernel(const int* __restrict__ ei, int E, int n) {
    int e = (blockIdx.x * blockDim.x + threadIdx.x) * 4;
    if (e + 4 <= E) {
        int4 c = *(const int4*)(ei + E + e);
        if ((unsigned)c.x < (unsigned)n) atomicAdd(&g_cnt[c.x], 1);
        if ((unsigned)c.y < (unsigned)n) atomicAdd(&g_cnt[c.y], 1);
        if ((unsigned)c.z < (unsigned)n) atomicAdd(&g_cnt[c.z], 1);
        if ((unsigned)c.w < (unsigned)n) atomicAdd(&g_cnt[c.w], 1);
    } else {
        for (; e < E; e++) {
            int c = ei[E + e];
            if ((unsigned)c < (unsigned)n) atomicAdd(&g_cnt[c], 1);
        }
    }
}

__global__ __launch_bounds__(1024) void scan_kernel(int n) {
    __shared__ int s[1024];
    const int t = threadIdx.x;
    const int C = (n + 1023) / 1024;
    const int start = t * C, end = min(start + C, n);
    int sum = 0;
    for (int i = start; i < end; i++) sum += g_cnt[i];
    s[t] = sum;
    __syncthreads();
    for (int off = 1; off < 1024; off <<= 1) {
        int v = s[t];
        int o = (t >= off) ? s[t - off] : 0;
        __syncthreads();
        s[t] = v + o;
        __syncthreads();
    }
    int run = s[t] - sum;
    for (int i = start; i < end; i++) {
        g_rowptr[i] = run;
        g_wr[i] = run;
        g_dinv[i] = rsqrtf((float)(g_cnt[i] + 1));
        run += g_cnt[i];
    }
    if (t == 0) g_rowptr[n] = s[1023];
}

__global__ void place_kernel(const int* __restrict__ ei, int E, int n) {
    int e = (blockIdx.x * blockDim.x + threadIdx.x) * 4;
    if (e + 4 <= E) {
        int4 c = *(const int4*)(ei + E + e);
        int4 r = *(const int4*)(ei + e);
        if ((unsigned)c.x < (unsigned)n && (unsigned)r.x < (unsigned)n)
            g_srcidx[atomicAdd(&g_wr[c.x], 1)] = r.x;
        if ((unsigned)c.y < (unsigned)n && (unsigned)r.y < (unsigned)n)
            g_srcidx[atomicAdd(&g_wr[c.y], 1)] = r.y;
        if ((unsigned)c.z < (unsigned)n && (unsigned)r.z < (unsigned)n)
            g_srcidx[atomicAdd(&g_wr[c.z], 1)] = r.z;
        if ((unsigned)c.w < (unsigned)n && (unsigned)r.w < (unsigned)n)
            g_srcidx[atomicAdd(&g_wr[c.w], 1)] = r.w;
    } else {
        for (; e < E; e++) {
            int c = ei[E + e], r = ei[e];
            if ((unsigned)c < (unsigned)n && (unsigned)r < (unsigned)n)
                g_srcidx[atomicAdd(&g_wr[c], 1)] = r;
        }
    }
}

// ---------------------------------------------------------------------------
// Gather (R12-proven): one warp per node, float4 per lane, 8/4/1 ladder.
// Fused relu/bias/dinv; emits packed bf16x2 hi/lo planes.
// ---------------------------------------------------------------------------
__global__ __launch_bounds__(256) void gather_kernel(int layer, int n,
                                                     const float* __restrict__ bias) {
    int node = (blockIdx.x * blockDim.x + threadIdx.x) >> 5;
    int lane = threadIdx.x & 31;
    if (node >= n) return;

    const float* __restrict__ h = (layer == 0) ? g_g1 : g_g2;
    uint32_t* __restrict__ oh = (layer == 0) ? g_x1ph : g_y2ph;
    uint32_t* __restrict__ ol = (layer == 0) ? g_x1pl : g_y2pl;

    size_t base = (size_t)node * D + lane * 4;
    float dn = g_dinv[node];
    float4 sv = *(const float4*)(h + base);
    float4 acc = make_float4(sv.x * dn, sv.y * dn, sv.z * dn, sv.w * dn);

    int s = g_rowptr[node], e = g_rowptr[node + 1];
    int i = s;
    for (; i + 8 <= e; i += 8) {
        int si[8]; float di[8]; float4 vi[8];
#pragma unroll
        for (int j = 0; j < 8; j++) si[j] = g_srcidx[i + j];
#pragma unroll
        for (int j = 0; j < 8; j++) di[j] = g_dinv[si[j]];
#pragma unroll
        for (int j = 0; j < 8; j++)
            vi[j] = *(const float4*)(h + (size_t)si[j] * D + lane * 4);
#pragma unroll
        for (int j = 0; j < 8; j++) {
            acc.x += vi[j].x * di[j];
            acc.y += vi[j].y * di[j];
            acc.z += vi[j].z * di[j];
            acc.w += vi[j].w * di[j];
        }
    }
    for (; i + 4 <= e; i += 4) {
        int si[4]; float di[4]; float4 vi[4];
#pragma unroll
        for (int j = 0; j < 4; j++) si[j] = g_srcidx[i + j];
#pragma unroll
        for (int j = 0; j < 4; j++) di[j] = g_dinv[si[j]];
#pragma unroll
        for (int j = 0; j < 4; j++)
            vi[j] = *(const float4*)(h + (size_t)si[j] * D + lane * 4);
#pragma unroll
        for (int j = 0; j < 4; j++) {
            acc.x += vi[j].x * di[j];
            acc.y += vi[j].y * di[j];
            acc.z += vi[j].z * di[j];
            acc.w += vi[j].w * di[j];
        }
    }
    for (; i < e; i++) {
        int src = g_srcidx[i];
        float ds = g_dinv[src];
        float4 v = *(const float4*)(h + (size_t)src * D + lane * 4);
        acc.x += v.x * ds; acc.y += v.y * ds; acc.z += v.z * ds; acc.w += v.w * ds;
    }
    float4 bb = *(const float4*)(bias + lane * 4);
    float r0 = fmaxf(fmaf(dn, acc.x, bb.x), 0.f);
    float r1 = fmaxf(fmaf(dn, acc.y, bb.y), 0.f);
    float r2 = fmaxf(fmaf(dn, acc.z, bb.z), 0.f);
    float r3 = fmaxf(fmaf(dn, acc.w, bb.w), 0.f);
    uint2 hh, ll;
    split2(r0, r1, hh.x, ll.x);
    split2(r2, r3, hh.y, ll.y);
    *(uint2*)(oh + (size_t)node * 64 + lane * 2) = hh;
    *(uint2*)(ol + (size_t)node * 64 + lane * 2) = ll;
}

// ---------------------------------------------------------------------------
// bf16 m16n8k16 tensor GEMM, 3-term hi/lo split, cp.async double-buffered.
// Block 256 thr (8 warps), tile 128(M)x128(N); warp w: m0w=(w&3)*32, n0w=(w>>2)*64.
// smem: [buf 2][plane 4: Ah,Al,Bh,Bl][128 rows x SROW], row-major [m][k2].
// K-chunk = 8 k2 (one m16n8k16 step).  Fragments:
//   a0=A[mm][q4] a1=A[mm+8][q4] a2=A[mm][q4+4] a3=A[mm+8][q4+4]
//   b0=B[nn][q4] b1=B[nn][q4+4]
// MODE 0: A = fp32 x (split inline, manual STS), B=W1 -> g_g1.
// MODE 1: A = x1 planes (cp.async),  B=W2 -> g_g2.
// MODE 2: K2=128: A = x1|y2 planes,  B=Wl -> out+bl.
// ---------------------------------------------------------------------------
__device__ __forceinline__ void mma16(float* c, const uint32_t* a,
                                      uint32_t b0, uint32_t b1) {
    asm("mma.sync.aligned.m16n8k16.row.col.f32.bf16.bf16.f32 "
        "{%0,%1,%2,%3}, {%4,%5,%6,%7}, {%8,%9}, {%0,%1,%2,%3};"
        : "+f"(c[0]), "+f"(c[1]), "+f"(c[2]), "+f"(c[3])
        : "r"(a[0]), "r"(a[1]), "r"(a[2]), "r"(a[3]), "r"(b0), "r"(b1));
}

#define PLANE_U32 (128 * SROW)

template <int MODE>
__global__ __launch_bounds__(256, 2) void gemm_bf16(
    const float* __restrict__ Ax,        // MODE0: fp32 x
    const float* __restrict__ bias_out,  // MODE2: bl
    float* __restrict__ outp,            // MODE2: out
    int n)
{
    constexpr int K2 = (MODE == 2) ? 128 : 64;
    constexpr int NCH = K2 / 8;
    __shared__ uint32_t sm[2][4][PLANE_U32];   // 48 KB exactly
    const uint32_t smbase = (uint32_t)__cvta_generic_to_shared(&sm[0][0][0]);

    const int t = threadIdx.x;
    const int lane = t & 31, w = t >> 5;
    const int g = lane >> 2, q4 = lane & 3;
    const int m0w = (w & 3) * 32, n0w = (w >> 2) * 64;
    const int m0 = blockIdx.x * 128;

    float acc[2][8][4];
#pragma unroll
    for (int i = 0; i < 2; i++)
#pragma unroll
        for (int j = 0; j < 8; j++)
#pragma unroll
            for (int k = 0; k < 4; k++) acc[i][j][k] = 0.0f;

#define STAGE(cc, bb) do {                                                     \
    const int k2off_ = (cc) * 8;                                               \
    {   /* B planes: cp.async */                                               \
        int m_ = t >> 1, hh_ = t & 1;                                          \
        const uint32_t *bsh_, *bsl_; int bstr_;                                \
        if (MODE == 0)      { bsh_ = g_w1ph; bsl_ = g_w1pl; bstr_ = 64; }      \
        else if (MODE == 1) { bsh_ = g_w2ph; bsl_ = g_w2pl; bstr_ = 64; }      \
        else                { bsh_ = g_wlph; bsl_ = g_wlpl; bstr_ = 128; }     \
        uint32_t off_ = (uint32_t)(m_ * SROW + hh_ * 4) * 4;                   \
        cpa16(smbase + ((bb) * 4 + 2) * (PLANE_U32 * 4) + off_,                \
              bsh_ + (size_t)m_ * bstr_ + k2off_ + hh_ * 4, 16);               \
        cpa16(smbase + ((bb) * 4 + 3) * (PLANE_U32 * 4) + off_,                \
              bsl_ + (size_t)m_ * bstr_ + k2off_ + hh_ * 4, 16);               \
    }                                                                          \
    if (MODE == 0) {  /* A: manual fp32 split */                               \
        _Pragma("unroll")                                                      \
        for (int i_ = 0; i_ < 2; i_++) {                                       \
            int idx_ = t + i_ * 256, m_ = idx_ >> 2, q_ = idx_ & 3;            \
            int gm_ = m0 + m_;                                                 \
            float4 v_ = make_float4(0.f, 0.f, 0.f, 0.f);                       \
            if (gm_ < n)                                                       \
                v_ = *(const float4*)(Ax + (size_t)gm_ * D + k2off_ * 2 + q_ * 4); \
            uint32_t h0_, l0_, h1_, l1_;                                       \
            split2(v_.x, v_.y, h0_, l0_);                                      \
            split2(v_.z, v_.w, h1_, l1_);                                      \
            *(uint2*)&sm[bb][0][m_ * SROW + 2 * q_] = make_uint2(h0_, h1_);    \
            *(uint2*)&sm[bb][1][m_ * SROW + 2 * q_] = make_uint2(l0_, l1_);    \
        }                                                                      \
    } else {          /* A: cp.async from planes */                            \
        int m_ = t >> 1, hh_ = t & 1;                                          \
        int gm_ = m0 + m_;                                                     \
        const uint32_t *ash_, *asl_; int aoff_ = k2off_;                       \
        if (MODE == 1) { ash_ = g_x1ph; asl_ = g_x1pl; }                       \
        else if (k2off_ < 64) { ash_ = g_x1ph; asl_ = g_x1pl; }                \
        else { ash_ = g_y2ph; asl_ = g_y2pl; aoff_ = k2off_ - 64; }            \
        bool v_ = gm_ < n; int gmc_ = v_ ? gm_ : 0;                            \
        uint32_t off_ = (uint32_t)(m_ * SROW + hh_ * 4) * 4;                   \
        cpa16(smbase + ((bb) * 4 + 0) * (PLANE_U32 * 4) + off_,                \
              ash_ + (size_t)gmc_ * 64 + aoff_ + hh_ * 4, v_ ? 16 : 0);        \
        cpa16(smbase + ((bb) * 4 + 1) * (PLANE_U32 * 4) + off_,                \
              asl_ + (size_t)gmc_ * 64 + aoff_ + hh_ * 4, v_ ? 16 : 0);        \
    }                                                                          \
    asm volatile("cp.async.commit_group;" ::: "memory");                       \
} while (0)

    STAGE(0, 0);
    for (int ch = 0; ch < NCH; ch++) {
        int nxt = ch + 1;
        if (nxt < NCH) {
            STAGE(nxt, nxt & 1);
            asm volatile("cp.async.wait_group 1;" ::: "memory");
        } else {
            asm volatile("cp.async.wait_group 0;" ::: "memory");
        }
        __syncthreads();

        const uint32_t* Ah = sm[ch & 1][0];
        const uint32_t* Al = sm[ch & 1][1];
        const uint32_t* Bh = sm[ch & 1][2];
        const uint32_t* Bl = sm[ch & 1][3];

        uint32_t ahf[2][4], alf[2][4];
#pragma unroll
        for (int ma = 0; ma < 2; ma++) {
            int mm = m0w + ma * 16 + g;
            ahf[ma][0] = Ah[mm * SROW + q4];
            ahf[ma][1] = Ah[(mm + 8) * SROW + q4];
            ahf[ma][2] = Ah[mm * SROW + q4 + 4];
            ahf[ma][3] = Ah[(mm + 8) * SROW + q4 + 4];
            alf[ma][0] = Al[mm * SROW + q4];
            alf[ma][1] = Al[(mm + 8) * SROW + q4];
            alf[ma][2] = Al[mm * SROW + q4 + 4];
            alf[ma][3] = Al[(mm + 8) * SROW + q4 + 4];
        }
#pragma unroll
        for (int na = 0; na < 8; na++) {
            int nn = n0w + na * 8 + g;
            uint32_t bh0 = Bh[nn * SROW + q4];
            uint32_t bh1 = Bh[nn * SROW + q4 + 4];
            uint32_t bl0 = Bl[nn * SROW + q4];
            uint32_t bl1 = Bl[nn * SROW + q4 + 4];
#pragma unroll
            for (int ma = 0; ma < 2; ma++) {
                mma16(acc[ma][na], ahf[ma], bh0, bh1);   // hi*hi
                mma16(acc[ma][na], alf[ma], bh0, bh1);   // lo*hi
                mma16(acc[ma][na], ahf[ma], bl0, bl1);   // hi*lo
            }
        }
        __syncthreads();
    }
#undef STAGE

    // ---- epilogue ----
    float* dst = (MODE == 0) ? g_g1 : (MODE == 1) ? g_g2 : outp;
#pragma unroll
    for (int ma = 0; ma < 2; ma++) {
        int mlo = m0 + m0w + ma * 16 + g;
        int mhi = mlo + 8;
#pragma unroll
        for (int na = 0; na < 8; na++) {
            int nc = n0w + na * 8 + 2 * q4;
            float b0 = 0.f, b1 = 0.f;
            if (MODE == 2) { b0 = bias_out[nc]; b1 = bias_out[nc + 1]; }
            if (mlo < n) {
                float2 v = make_float2(acc[ma][na][0] + b0, acc[ma][na][1] + b1);
                *(float2*)(dst + (size_t)mlo * D + nc) = v;
            }
            if (mhi < n) {
                float2 v = make_float2(acc[ma][na][2] + b0, acc[ma][na][3] + b1);
                *(float2*)(dst + (size_t)mhi * D + nc) = v;
            }
        }
    }
}

// ---------------------------------------------------------------------------
// Launch: single stream, no host state, graph-capture safe.  9 launches.
// ---------------------------------------------------------------------------
extern "C" void kernel_launch(void* const* d_in, const int* in_sizes, int n_in,
                              void* d_out, int out_size)
{
    const float* x  = (const float*)d_in[0];
    const int*   ei = (const int*)d_in[1];      // int32
    const float* W1 = (const float*)d_in[2];
    const float* b1 = (const float*)d_in[3];
    const float* W2 = (const float*)d_in[4];
    const float* b2 = (const float*)d_in[5];
    const float* Wl = (const float*)d_in[6];
    const float* bl = (const float*)d_in[7];
    float* out = (float*)d_out;

    const int n = in_sizes[0] / D;   // 50000
    const int E = in_sizes[1] / 2;   // 600000

    const int prep_threads = (n > 32768) ? n : 32768;
    const int e4blocks = ((E + 3) / 4 + 255) / 256;
    const int gblocks = (n + 127) / 128;
    const int wblocks = (n + 7) / 8;

    prep_kernel<<<(prep_threads + 255) / 256, 256>>>(W1, W2, Wl, n);
    hist_kernel<<<e4blocks, 256>>>(ei, E, n);
    scan_kernel<<<1, 1024>>>(n);
    place_kernel<<<e4blocks, 256>>>(ei, E, n);

    gemm_bf16<0><<<gblocks, 256>>>(x, nullptr, nullptr, n);
    gather_kernel<<<wblocks, 256>>>(0, n, b1);
    gemm_bf16<1><<<gblocks, 256>>>(nullptr, nullptr, nullptr, n);
    gather_kernel<<<wblocks, 256>>>(1, n, b2);
    gemm_bf16<2><<<gblocks, 256>>>(nullptr, bl, out, n);
}

// round 17
// speedup vs baseline: 1.1524x; 1.0456x over previous
#include <cuda_runtime.h>
#include <cuda_bf16.h>
#include <cstdint>
#include <cstddef>

#define NMAX 50000
#define EMAX 600000
#define D 128
#define SROW 12   // smem row stride in u32: 8 k2 + 4 pad (conflict-free)

// ---------------------------------------------------------------------------
// Device scratch.  "p" buffers are packed bf16x2 planes: [row][k2] uint32.
// ---------------------------------------------------------------------------
__device__ __align__(16) float g_dinv[NMAX];
__device__ __align__(16) float g_g1[NMAX * D];   // h1 = x@W1 fp32
__device__ __align__(16) float g_g2[NMAX * D];   // h2 = x1@W2 fp32
__device__ __align__(16) uint32_t g_x1ph[NMAX * 64], g_x1pl[NMAX * 64];
__device__ __align__(16) uint32_t g_y2ph[NMAX * 64], g_y2pl[NMAX * 64];
// weights transposed to [n][k2] planes
__device__ __align__(16) uint32_t g_w1ph[128 * 64],  g_w1pl[128 * 64];
__device__ __align__(16) uint32_t g_w2ph[128 * 64],  g_w2pl[128 * 64];
__device__ __align__(16) uint32_t g_wlph[128 * 128], g_wlpl[128 * 128];
// CSR (by destination).  g_cnt is zero at load and re-zeroed by gemm3 every
// pass, so hist may legally run first in each invocation.
__device__ int g_cnt[NMAX];
__device__ int g_wr[NMAX];
__device__ int g_rowptr[NMAX + 1];
__device__ int g_srcidx[EMAX];

// bf16 split: pack 2 floats -> hi bf16x2 + lo bf16x2 (low 16 bits = first val)
__device__ __forceinline__ void split2(float a, float b, uint32_t& hi, uint32_t& lo) {
    __nv_bfloat16 ha = __float2bfloat16_rn(a), hb = __float2bfloat16_rn(b);
    float ra = a - __bfloat162float(ha), rb = b - __bfloat162float(hb);
    __nv_bfloat16 la = __float2bfloat16_rn(ra), lb = __float2bfloat16_rn(rb);
    hi = (uint32_t)__bfloat16_as_ushort(ha) | ((uint32_t)__bfloat16_as_ushort(hb) << 16);
    lo = (uint32_t)__bfloat16_as_ushort(la) | ((uint32_t)__bfloat16_as_ushort(lb) << 16);
}

__device__ __forceinline__ void cpa16(uint32_t dst, const void* src, int szbytes) {
    asm volatile("cp.async.cg.shared.global [%0], [%1], 16, %2;"
                 :: "r"(dst), "l"(src), "r"(szbytes) : "memory");
}

// ---------------------------------------------------------------------------
// prep (W planes) + hist fused: blocks [0,128) prep, rest hist (4 edges/thr).
// ---------------------------------------------------------------------------
__device__ __forceinline__ void hist_body(int bid, const int* __restrict__ ei,
                                          int E, int n) {
    int e = (bid * 256 + threadIdx.x) * 4;
    if (e + 4 <= E) {
        int4 c = *(const int4*)(ei + E + e);
        if ((unsigned)c.x < (unsigned)n) atomicAdd(&g_cnt[c.x], 1);
        if ((unsigned)c.y < (unsigned)n) atomicAdd(&g_cnt[c.y], 1);
        if ((unsigned)c.z < (unsigned)n) atomicAdd(&g_cnt[c.z], 1);
        if ((unsigned)c.w < (unsigned)n) atomicAdd(&g_cnt[c.w], 1);
    } else {
        for (; e < E; e++) {
            int c = ei[E + e];
            if ((unsigned)c < (unsigned)n) atomicAdd(&g_cnt[c], 1);
        }
    }
}

__global__ void prep_hist_kernel(const float* __restrict__ W1,
                                 const float* __restrict__ W2,
                                 const float* __restrict__ Wl,
                                 const int* __restrict__ ei, int E, int n) {
    if ((int)blockIdx.x >= 128) {
        hist_body(blockIdx.x - 128, ei, E, n);
        return;
    }
    int idx = blockIdx.x * blockDim.x + threadIdx.x;
    if (idx < 8192) {                       // W1 [128][128] -> [n][64]
        int nn = idx & 127, k2 = idx >> 7;
        uint32_t h, l;
        split2(W1[(2 * k2) * 128 + nn], W1[(2 * k2 + 1) * 128 + nn], h, l);
        g_w1ph[nn * 64 + k2] = h; g_w1pl[nn * 64 + k2] = l;
    } else if (idx < 16384) {               // W2
        int r = idx - 8192;
        int nn = r & 127, k2 = r >> 7;
        uint32_t h, l;
        split2(W2[(2 * k2) * 128 + nn], W2[(2 * k2 + 1) * 128 + nn], h, l);
        g_w2ph[nn * 64 + k2] = h; g_w2pl[nn * 64 + k2] = l;
    } else if (idx < 32768) {               // Wl [256][128] -> [n][128]
        int r = idx - 16384;
        int nn = r & 127, k2 = r >> 7;      // k2 in 0..127
        uint32_t h, l;
        split2(Wl[(2 * k2) * 128 + nn], Wl[(2 * k2 + 1) * 128 + nn], h, l);
        g_wlph[nn * 128 + k2] = h; g_wlpl[nn * 128 + k2] = l;
    }
}

__global__ __launch_bounds__(1024) void scan_kernel(int n) {
    __shared__ int s[1024];
    const int t = threadIdx.x;
    const int C = (n + 1023) / 1024;
    const int start = t * C, end = min(start + C, n);
    int sum = 0;
    for (int i = start; i < end; i++) sum += g_cnt[i];
    s[t] = sum;
    __syncthreads();
    for (int off = 1; off < 1024; off <<= 1) {
        int v = s[t];
        int o = (t >= off) ? s[t - off] : 0;
        __syncthreads();
        s[t] = v + o;
        __syncthreads();
    }
    int run = s[t] - sum;
    for (int i = start; i < end; i++) {
        g_rowptr[i] = run;
        g_wr[i] = run;
        g_dinv[i] = rsqrtf((float)(g_cnt[i] + 1));
        run += g_cnt[i];
    }
    if (t == 0) g_rowptr[n] = s[1023];
}

__device__ __forceinline__ void place_body(int bid, const int* __restrict__ ei,
                                           int E, int n) {
    int e = (bid * 256 + threadIdx.x) * 4;
    if (e + 4 <= E) {
        int4 c = *(const int4*)(ei + E + e);
        int4 r = *(const int4*)(ei + e);
        if ((unsigned)c.x < (unsigned)n && (unsigned)r.x < (unsigned)n)
            g_srcidx[atomicAdd(&g_wr[c.x], 1)] = r.x;
        if ((unsigned)c.y < (unsigned)n && (unsigned)r.y < (unsigned)n)
            g_srcidx[atomicAdd(&g_wr[c.y], 1)] = r.y;
        if ((unsigned)c.z < (unsigned)n && (unsigned)r.z < (unsigned)n)
            g_srcidx[atomicAdd(&g_wr[c.z], 1)] = r.z;
        if ((unsigned)c.w < (unsigned)n && (unsigned)r.w < (unsigned)n)
            g_srcidx[atomicAdd(&g_wr[c.w], 1)] = r.w;
    } else {
        for (; e < E; e++) {
            int c = ei[E + e], r = ei[e];
            if ((unsigned)c < (unsigned)n && (unsigned)r < (unsigned)n)
                g_srcidx[atomicAdd(&g_wr[c], 1)] = r;
        }
    }
}

// ---------------------------------------------------------------------------
// Gather (R12-proven): one warp per node, float4 per lane, 8/4/1 ladder.
// Fused relu/bias/dinv; emits packed bf16x2 hi/lo planes.
// ---------------------------------------------------------------------------
__global__ __launch_bounds__(256) void gather_kernel(int layer, int n,
                                                     const float* __restrict__ bias) {
    int node = (blockIdx.x * blockDim.x + threadIdx.x) >> 5;
    int lane = threadIdx.x & 31;
    if (node >= n) return;

    const float* __restrict__ h = (layer == 0) ? g_g1 : g_g2;
    uint32_t* __restrict__ oh = (layer == 0) ? g_x1ph : g_y2ph;
    uint32_t* __restrict__ ol = (layer == 0) ? g_x1pl : g_y2pl;

    size_t base = (size_t)node * D + lane * 4;
    float dn = g_dinv[node];
    float4 sv = *(const float4*)(h + base);
    float4 acc = make_float4(sv.x * dn, sv.y * dn, sv.z * dn, sv.w * dn);

    int s = g_rowptr[node], e = g_rowptr[node + 1];
    int i = s;
    for (; i + 8 <= e; i += 8) {
        int si[8]; float di[8]; float4 vi[8];
#pragma unroll
        for (int j = 0; j < 8; j++) si[j] = g_srcidx[i + j];
#pragma unroll
        for (int j = 0; j < 8; j++) di[j] = g_dinv[si[j]];
#pragma unroll
        for (int j = 0; j < 8; j++)
            vi[j] = *(const float4*)(h + (size_t)si[j] * D + lane * 4);
#pragma unroll
        for (int j = 0; j < 8; j++) {
            acc.x += vi[j].x * di[j];
            acc.y += vi[j].y * di[j];
            acc.z += vi[j].z * di[j];
            acc.w += vi[j].w * di[j];
        }
    }
    for (; i + 4 <= e; i += 4) {
        int si[4]; float di[4]; float4 vi[4];
#pragma unroll
        for (int j = 0; j < 4; j++) si[j] = g_srcidx[i + j];
#pragma unroll
        for (int j = 0; j < 4; j++) di[j] = g_dinv[si[j]];
#pragma unroll
        for (int j = 0; j < 4; j++)
            vi[j] = *(const float4*)(h + (size_t)si[j] * D + lane * 4);
#pragma unroll
        for (int j = 0; j < 4; j++) {
            acc.x += vi[j].x * di[j];
            acc.y += vi[j].y * di[j];
            acc.z += vi[j].z * di[j];
            acc.w += vi[j].w * di[j];
        }
    }
    for (; i < e; i++) {
        int src = g_srcidx[i];
        float ds = g_dinv[src];
        float4 v = *(const float4*)(h + (size_t)src * D + lane * 4);
        acc.x += v.x * ds; acc.y += v.y * ds; acc.z += v.z * ds; acc.w += v.w * ds;
    }
    float4 bb = *(const float4*)(bias + lane * 4);
    float r0 = fmaxf(fmaf(dn, acc.x, bb.x), 0.f);
    float r1 = fmaxf(fmaf(dn, acc.y, bb.y), 0.f);
    float r2 = fmaxf(fmaf(dn, acc.z, bb.z), 0.f);
    float r3 = fmaxf(fmaf(dn, acc.w, bb.w), 0.f);
    uint2 hh, ll;
    split2(r0, r1, hh.x, ll.x);
    split2(r2, r3, hh.y, ll.y);
    *(uint2*)(oh + (size_t)node * 64 + lane * 2) = hh;
    *(uint2*)(ol + (size_t)node * 64 + lane * 2) = ll;
}

// ---------------------------------------------------------------------------
// bf16 m16n8k16 tensor GEMM, 3-term hi/lo split, cp.async double-buffered.
// (R16-proven.)  Device body; thin global wrappers below.
// ---------------------------------------------------------------------------
__device__ __forceinline__ void mma16(float* c, const uint32_t* a,
                                      uint32_t b0, uint32_t b1) {
    asm("mma.sync.aligned.m16n8k16.row.col.f32.bf16.bf16.f32 "
        "{%0,%1,%2,%3}, {%4,%5,%6,%7}, {%8,%9}, {%0,%1,%2,%3};"
        : "+f"(c[0]), "+f"(c[1]), "+f"(c[2]), "+f"(c[3])
        : "r"(a[0]), "r"(a[1]), "r"(a[2]), "r"(a[3]), "r"(b0), "r"(b1));
}

#define PLANE_U32 (128 * SROW)

template <int MODE>
__device__ __forceinline__ void gemm_body(int bid,
    const float* __restrict__ Ax,        // MODE0: fp32 x
    const float* __restrict__ bias_out,  // MODE2: bl
    float* __restrict__ outp,            // MODE2: out
    int n)
{
    constexpr int K2 = (MODE == 2) ? 128 : 64;
    constexpr int NCH = K2 / 8;
    __shared__ uint32_t sm[2][4][PLANE_U32];   // 48 KB
    const uint32_t smbase = (uint32_t)__cvta_generic_to_shared(&sm[0][0][0]);

    const int t = threadIdx.x;
    const int lane = t & 31, w = t >> 5;
    const int g = lane >> 2, q4 = lane & 3;
    const int m0w = (w & 3) * 32, n0w = (w >> 2) * 64;
    const int m0 = bid * 128;

    float acc[2][8][4];
#pragma unroll
    for (int i = 0; i < 2; i++)
#pragma unroll
        for (int j = 0; j < 8; j++)
#pragma unroll
            for (int k = 0; k < 4; k++) acc[i][j][k] = 0.0f;

#define STAGE(cc, bb) do {                                                     \
    const int k2off_ = (cc) * 8;                                               \
    {   /* B planes: cp.async */                                               \
        int m_ = t >> 1, hh_ = t & 1;                                          \
        const uint32_t *bsh_, *bsl_; int bstr_;                                \
        if (MODE == 0)      { bsh_ = g_w1ph; bsl_ = g_w1pl; bstr_ = 64; }      \
        else if (MODE == 1) { bsh_ = g_w2ph; bsl_ = g_w2pl; bstr_ = 64; }      \
        else                { bsh_ = g_wlph; bsl_ = g_wlpl; bstr_ = 128; }     \
        uint32_t off_ = (uint32_t)(m_ * SROW + hh_ * 4) * 4;                   \
        cpa16(smbase + ((bb) * 4 + 2) * (PLANE_U32 * 4) + off_,                \
              bsh_ + (size_t)m_ * bstr_ + k2off_ + hh_ * 4, 16);               \
        cpa16(smbase + ((bb) * 4 + 3) * (PLANE_U32 * 4) + off_,                \
              bsl_ + (size_t)m_ * bstr_ + k2off_ + hh_ * 4, 16);               \
    }                                                                          \
    if (MODE == 0) {  /* A: manual fp32 split */                               \
        _Pragma("unroll")                                                      \
        for (int i_ = 0; i_ < 2; i_++) {                                       \
            int idx_ = t + i_ * 256, m_ = idx_ >> 2, q_ = idx_ & 3;            \
            int gm_ = m0 + m_;                                                 \
            float4 v_ = make_float4(0.f, 0.f, 0.f, 0.f);                       \
            if (gm_ < n)                                                       \
                v_ = *(const float4*)(Ax + (size_t)gm_ * D + k2off_ * 2 + q_ * 4); \
            uint32_t h0_, l0_, h1_, l1_;                                       \
            split2(v_.x, v_.y, h0_, l0_);                                      \
            split2(v_.z, v_.w, h1_, l1_);                                      \
            *(uint2*)&sm[bb][0][m_ * SROW + 2 * q_] = make_uint2(h0_, h1_);    \
            *(uint2*)&sm[bb][1][m_ * SROW + 2 * q_] = make_uint2(l0_, l1_);    \
        }                                                                      \
    } else {          /* A: cp.async from planes */                            \
        int m_ = t >> 1, hh_ = t & 1;                                          \
        int gm_ = m0 + m_;                                                     \
        const uint32_t *ash_, *asl_; int aoff_ = k2off_;                       \
        if (MODE == 1) { ash_ = g_x1ph; asl_ = g_x1pl; }                       \
        else if (k2off_ < 64) { ash_ = g_x1ph; asl_ = g_x1pl; }                \
        else { ash_ = g_y2ph; asl_ = g_y2pl; aoff_ = k2off_ - 64; }            \
        bool v_ = gm_ < n; int gmc_ = v_ ? gm_ : 0;                            \
        uint32_t off_ = (uint32_t)(m_ * SROW + hh_ * 4) * 4;                   \
        cpa16(smbase + ((bb) * 4 + 0) * (PLANE_U32 * 4) + off_,                \
              ash_ + (size_t)gmc_ * 64 + aoff_ + hh_ * 4, v_ ? 16 : 0);        \
        cpa16(smbase + ((bb) * 4 + 1) * (PLANE_U32 * 4) + off_,                \
              asl_ + (size_t)gmc_ * 64 + aoff_ + hh_ * 4, v_ ? 16 : 0);        \
    }                                                                          \
    asm volatile("cp.async.commit_group;" ::: "memory");                       \
} while (0)

    STAGE(0, 0);
    for (int ch = 0; ch < NCH; ch++) {
        int nxt = ch + 1;
        if (nxt < NCH) {
            STAGE(nxt, nxt & 1);
            asm volatile("cp.async.wait_group 1;" ::: "memory");
        } else {
            asm volatile("cp.async.wait_group 0;" ::: "memory");
        }
        __syncthreads();

        const uint32_t* Ah = sm[ch & 1][0];
        const uint32_t* Al = sm[ch & 1][1];
        const uint32_t* Bh = sm[ch & 1][2];
        const uint32_t* Bl = sm[ch & 1][3];

        uint32_t ahf[2][4], alf[2][4];
#pragma unroll
        for (int ma = 0; ma < 2; ma++) {
            int mm = m0w + ma * 16 + g;
            ahf[ma][0] = Ah[mm * SROW + q4];
            ahf[ma][1] = Ah[(mm + 8) * SROW + q4];
            ahf[ma][2] = Ah[mm * SROW + q4 + 4];
            ahf[ma][3] = Ah[(mm + 8) * SROW + q4 + 4];
            alf[ma][0] = Al[mm * SROW + q4];
            alf[ma][1] = Al[(mm + 8) * SROW + q4];
            alf[ma][2] = Al[mm * SROW + q4 + 4];
            alf[ma][3] = Al[(mm + 8) * SROW + q4 + 4];
        }
#pragma unroll
        for (int na = 0; na < 8; na++) {
            int nn = n0w + na * 8 + g;
            uint32_t bh0 = Bh[nn * SROW + q4];
            uint32_t bh1 = Bh[nn * SROW + q4 + 4];
            uint32_t bl0 = Bl[nn * SROW + q4];
            uint32_t bl1 = Bl[nn * SROW + q4 + 4];
#pragma unroll
            for (int ma = 0; ma < 2; ma++) {
                mma16(acc[ma][na], ahf[ma], bh0, bh1);   // hi*hi
                mma16(acc[ma][na], alf[ma], bh0, bh1);   // lo*hi
                mma16(acc[ma][na], ahf[ma], bl0, bl1);   // hi*lo
            }
        }
        __syncthreads();
    }
#undef STAGE

    // ---- epilogue ----
    float* dst = (MODE == 0) ? g_g1 : (MODE == 1) ? g_g2 : outp;
#pragma unroll
    for (int ma = 0; ma < 2; ma++) {
        int mlo = m0 + m0w + ma * 16 + g;
        int mhi = mlo + 8;
#pragma unroll
        for (int na = 0; na < 8; na++) {
            int nc = n0w + na * 8 + 2 * q4;
            float b0 = 0.f, b1 = 0.f;
            if (MODE == 2) { b0 = bias_out[nc]; b1 = bias_out[nc + 1]; }
            if (mlo < n) {
                float2 v = make_float2(acc[ma][na][0] + b0, acc[ma][na][1] + b1);
                *(float2*)(dst + (size_t)mlo * D + nc) = v;
            }
            if (mhi < n) {
                float2 v = make_float2(acc[ma][na][2] + b0, acc[ma][na][3] + b1);
                *(float2*)(dst + (size_t)mhi * D + nc) = v;
            }
        }
    }
}

// gemm1 + place fused: blocks [0,gb) gemm MODE0, rest place (CSR fill).
__global__ __launch_bounds__(256, 2) void k_gemm1_place(
    const float* __restrict__ x, const int* __restrict__ ei, int E, int n, int gb)
{
    if ((int)blockIdx.x < gb)
        gemm_body<0>(blockIdx.x, x, nullptr, nullptr, n);
    else
        place_body(blockIdx.x - gb, ei, E, n);
}

__global__ __launch_bounds__(256, 2) void k_gemm2(int n)
{
    gemm_body<1>(blockIdx.x, nullptr, nullptr, nullptr, n);
}

// gemm3; also re-zeroes g_cnt for the next pass.
__global__ __launch_bounds__(256, 2) void k_gemm3(
    const float* __restrict__ bl, float* __restrict__ out, int n)
{
    for (int i = blockIdx.x * blockDim.x + threadIdx.x; i < n;
         i += gridDim.x * blockDim.x)
        g_cnt[i] = 0;
    gemm_body<2>(blockIdx.x, nullptr, bl, out, n);
}

// ---------------------------------------------------------------------------
// Launch: single stream, no host state, graph-capture safe.  7 launches.
// ---------------------------------------------------------------------------
extern "C" void kernel_launch(void* const* d_in, const int* in_sizes, int n_in,
                              void* d_out, int out_size)
{
    const float* x  = (const float*)d_in[0];
    const int*   ei = (const int*)d_in[1];      // int32
    const float* W1 = (const float*)d_in[2];
    const float* b1 = (const float*)d_in[3];
    const float* W2 = (const float*)d_in[4];
    const float* b2 = (const float*)d_in[5];
    const float* Wl = (const float*)d_in[6];
    const float* bl = (const float*)d_in[7];
    float* out = (float*)d_out;

    const int n = in_sizes[0] / D;   // 50000
    const int E = in_sizes[1] / 2;   // 600000

    const int e4blocks = ((E + 3) / 4 + 255) / 256;
    const int gblocks = (n + 127) / 128;
    const int wblocks = (n + 7) / 8;

    prep_hist_kernel<<<128 + e4blocks, 256>>>(W1, W2, Wl, ei, E, n);
    scan_kernel<<<1, 1024>>>(n);
    k_gemm1_place<<<gblocks + e4blocks, 256>>>(x, ei, E, n, gblocks);
    gather_kernel<<<wblocks, 256>>>(0, n, b1);
    k_gemm2<<<gblocks, 256>>>(n);
    gather_kernel<<<wblocks, 256>>>(1, n, b2);
    k_gemm3<<<gblocks, 256>>>(bl, out, n);
}